// round 14
// baseline (speedup 1.0000x reference)
#include <cuda_runtime.h>
#include <math.h>
#include <stdint.h>

#define B_   64
#define T_   20
#define N_   100
#define F_   64
#define H_   256
#define BT_  (B_*T_)        // 1280
#define BTN_ (B_*T_*N_)     // 128000
#define NP_  128            // padded node count (M side)
#define KP_  112            // padded node count (K side, 7x16)
#define LN_EPS 1e-5f

typedef unsigned long long u64;

// ---------------- f32x2 packed-math helpers (sm_103a) ----------------------
__device__ __forceinline__ u64 fma2(u64 a, u64 b, u64 c) {
    u64 d;
    asm("fma.rn.f32x2 %0, %1, %2, %3;" : "=l"(d) : "l"(a), "l"(b), "l"(c));
    return d;
}
__device__ __forceinline__ u64 dup2(float x) {
    u64 d;
    asm("mov.b64 %0, {%1, %1};" : "=l"(d) : "f"(x));
    return d;
}
__device__ __forceinline__ float2 unpack2(u64 v) {
    float2 r;
    asm("mov.b64 {%0, %1}, %2;" : "=f"(r.x), "=f"(r.y) : "l"(v));
    return r;
}

// ---------------- cp.async helpers -----------------------------------------
__device__ __forceinline__ void cp_async16(uint32_t sa, const void* gp) {
    asm volatile("cp.async.ca.shared.global [%0], [%1], 16;" :: "r"(sa), "l"(gp));
}
__device__ __forceinline__ void cp_commit() {
    asm volatile("cp.async.commit_group;");
}
__device__ __forceinline__ void cp_wait0() {
    asm volatile("cp.async.wait_group 0;");
}

// ---------------- scratch (static device globals; no allocation) ----------
__device__ float g_x   [NP_*BT_*F_];     // x transposed, node-major (rows>=100 zero)
__device__ float g_m   [N_*BT_*H_];      // msg / attn scratch
__device__ float g_h0  [NP_*BT_*H_];     // node-padded rows stay zero
__device__ float g_h1  [NP_*BT_*H_];
__device__ float g_qv  [BTN_*H_];        // q' = h @ (Wq Wk^T)
__device__ float g_adjp[NP_*KP_];        // zero-padded adjacency [128][112]
__device__ float g_wkt [H_*H_];          // Wk^T
__device__ float g_mqk [H_*H_];          // Wq @ Wk^T
__device__ float g_wvp [H_*H_];          // Wv @ Wp
__device__ float g_u   [H_];             // Wk @ bq
__device__ float g_bvp [H_];             // bv @ Wp + bp

// ---------------- merged misc prep ----------------------------------------
// blocks [0,56):    adjp[n*112+m] (128x112, zero-padded)
// blocks [56,312):  wkt[o*256+g] = Wk[g*256+o]
// blocks [312,344): u[g] = Wk[g,:]·bq  (warp per g)
// block  344:       bvp[o] = bp[o] + sum_f bv[f]*Wp[f][o]
__global__ void prep_misc(const float* __restrict__ adj,
                          const float* __restrict__ Wk,
                          const float* __restrict__ bq,
                          const float* __restrict__ bv,
                          const float* __restrict__ Wp,
                          const float* __restrict__ bp,
                          float* __restrict__ adjp, float* __restrict__ wkt,
                          float* __restrict__ u, float* __restrict__ bvp) {
    const int tid = threadIdx.x;
    const int blk = blockIdx.x;
    if (blk < 56) {
        int i = blk * 256 + tid;                  // 128*112 = 14336
        if (i < NP_*KP_) {
            int n = i / KP_, m2 = i - n * KP_;
            adjp[i] = (n < N_ && m2 < N_) ? adj[n * N_ + m2] : 0.f;
        }
    } else if (blk < 312) {
        int i = (blk - 56) * 256 + tid;           // 65536
        int o = i >> 8, g = i & 255;
        wkt[i] = Wk[g * H_ + o];
    } else if (blk < 344) {
        const int g = (blk - 312) * 8 + (tid >> 5);
        const int lane = tid & 31;
        float s = 0.f;
#pragma unroll
        for (int i = 0; i < 8; i++) {
            int o = lane + 32 * i;
            s = fmaf(Wk[g * H_ + o], bq[o], s);
        }
#pragma unroll
        for (int off = 16; off; off >>= 1)
            s += __shfl_xor_sync(0xffffffffu, s, off);
        if (lane == 0) u[g] = s;
    } else {
        const int o = tid;
        float s0 = bp[o], s1 = 0.f, s2 = 0.f, s3 = 0.f;
        for (int f = 0; f < H_; f += 4) {
            s0 = fmaf(bv[f+0], Wp[(f+0) * H_ + o], s0);
            s1 = fmaf(bv[f+1], Wp[(f+1) * H_ + o], s1);
            s2 = fmaf(bv[f+2], Wp[(f+2) * H_ + o], s2);
            s3 = fmaf(bv[f+3], Wp[(f+3) * H_ + o], s3);
        }
        bvp[o] = (s0 + s1) + (s2 + s3);
    }
}

// x[b,t,n,f] -> g_x[(n*BT + bt)*F + f]
__global__ void xpose_kernel(const float* __restrict__ x, float* __restrict__ xT) {
    int idx = blockIdx.x * 256 + threadIdx.x;
    if (idx >= BTN_ * (F_/4)) return;
    int c   = idx & 15;
    int row = idx >> 4;            // bt*100 + n
    int n   = row % N_;
    int bt  = row / N_;
    ((float4*)xT)[(n * BT_ + bt) * (F_/4) + c] = ((const float4*)x)[idx];
}

// ---------------- SGEMM: 128 threads, 16x8 thread tile, f32x2 core ---------
// C[M,Nn] = A[M,K] @ B[K,Nn] (+bias)(relu)(+res). 128x128 CTA tile, Kstep 16.
template<bool BIAS, bool RELU, bool RES, bool MG>
__global__ void __launch_bounds__(128, 3) sgemm_kernel(
    const float* __restrict__ A, const float* __restrict__ Bm,
    const float* __restrict__ bias, const float* __restrict__ res,
    float* __restrict__ C, int M, int Nn, int K, int Mvalid) {
    __shared__ __align__(16) float As[2][16][132];
    __shared__ __align__(16) float Bs[2][16][128];

    const int tid = threadIdx.x;
    const int bx = blockIdx.x, by = blockIdx.y;
    const int arow = tid;                              // one A row per thread
    const int brow = tid >> 5, bcol = (tid & 31) << 2; // B: 4 rows per pass
    const int tx = tid & 15, ty = tid >> 4;

    const float* Ap = A + ((size_t)by * 128 + arow) * K;
    const float* Bp = Bm + (size_t)brow * Nn + (size_t)bx * 128 + bcol;

    uint32_t bdst0 = (uint32_t)__cvta_generic_to_shared(&Bs[0][brow][bcol]);
    uint32_t bdst1 = (uint32_t)__cvta_generic_to_shared(&Bs[1][brow][bcol]);

    u64 acc[16][4];
#pragma unroll
    for (int i = 0; i < 16; i++)
#pragma unroll
        for (int j = 0; j < 4; j++) acc[i][j] = 0ull;

    // prologue: k-block 0 -> buf 0
    {
#pragma unroll
        for (int c = 0; c < 4; c++) {
            float4 av = *(const float4*)(Ap + c * 4);
            As[0][c*4+0][arow] = av.x;
            As[0][c*4+1][arow] = av.y;
            As[0][c*4+2][arow] = av.z;
            As[0][c*4+3][arow] = av.w;
        }
#pragma unroll
        for (int i = 0; i < 4; i++)
            cp_async16(bdst0 + i * 4 * 128 * 4, Bp + (size_t)(i * 4) * Nn);
        cp_commit();
        cp_wait0();
    }
    __syncthreads();

    int buf = 0;
    for (int k0 = 16; k0 <= K; k0 += 16) {
        const bool more = (k0 < K);
        float4 av[4];
        if (more) {
#pragma unroll
            for (int c = 0; c < 4; c++)
                av[c] = *(const float4*)(Ap + k0 + c * 4);
            uint32_t bd = buf ? bdst0 : bdst1;   // next buffer
#pragma unroll
            for (int i = 0; i < 4; i++)
                cp_async16(bd + i * 4 * 128 * 4,
                           Bp + (size_t)(k0 + i * 4) * Nn);
            cp_commit();
        }

        const float (*Asb)[132] = As[buf];
        const float (*Bsb)[128] = Bs[buf];
#pragma unroll
        for (int kk = 0; kk < 16; kk++) {
            float a[16];
            *(float4*)(a)    = *(const float4*)&Asb[kk][ty*16];
            *(float4*)(a+4)  = *(const float4*)&Asb[kk][ty*16+4];
            *(float4*)(a+8)  = *(const float4*)&Asb[kk][ty*16+8];
            *(float4*)(a+12) = *(const float4*)&Asb[kk][ty*16+12];
            ulonglong2 bp0 = *(const ulonglong2*)&Bsb[kk][tx*4];
            ulonglong2 bp1 = *(const ulonglong2*)&Bsb[kk][64 + tx*4];
            u64 b2[4] = { bp0.x, bp0.y, bp1.x, bp1.y };
#pragma unroll
            for (int i = 0; i < 16; i++) {
                u64 ad = dup2(a[i]);
#pragma unroll
                for (int j = 0; j < 4; j++)
                    acc[i][j] = fma2(ad, b2[j], acc[i][j]);
            }
        }

        if (more) {
            const int nb = buf ^ 1;
#pragma unroll
            for (int c = 0; c < 4; c++) {
                As[nb][c*4+0][arow] = av[c].x;
                As[nb][c*4+1][arow] = av[c].y;
                As[nb][c*4+2][arow] = av[c].z;
                As[nb][c*4+3][arow] = av[c].w;
            }
            cp_wait0();
            __syncthreads();
            buf = nb;
        }
    }

    const int crow0 = by * 128 + ty * 16;
    const int c0 = bx * 128 + tx * 4;
#pragma unroll
    for (int i = 0; i < 16; i++) {
        if (MG && (crow0 + i) >= Mvalid) continue;
        size_t rbase = (size_t)(crow0 + i) * Nn;
#pragma unroll
        for (int g = 0; g < 2; g++) {
            const int col = c0 + g * 64;
            float2 p0 = unpack2(acc[i][g*2 + 0]);
            float2 p1 = unpack2(acc[i][g*2 + 1]);
            float4 o;
            o.x = p0.x; o.y = p0.y; o.z = p1.x; o.w = p1.y;
            if (BIAS) {
                o.x += bias[col + 0];
                o.y += bias[col + 1];
                o.z += bias[col + 2];
                o.w += bias[col + 3];
            }
            if (RELU) {
                o.x = fmaxf(o.x, 0.f); o.y = fmaxf(o.y, 0.f);
                o.z = fmaxf(o.z, 0.f); o.w = fmaxf(o.w, 0.f);
            }
            if (RES) {
                float4 r = *(const float4*)(res + rbase + col);
                o.x += r.x; o.y += r.y; o.z += r.z; o.w += r.w;
            }
            *(float4*)(C + rbase + col) = o;
        }
    }
}

// fused prep GEMM (256-thread body, tiny): z=0 -> mqk, z=1 -> wvp
__global__ void __launch_bounds__(256, 2) prep_gemm(
    const float* __restrict__ Wq, const float* __restrict__ wkt,
    const float* __restrict__ Wv, const float* __restrict__ Wp,
    float* __restrict__ mqk, float* __restrict__ wvp) {
    __shared__ __align__(16) float As[2][16][132];
    __shared__ __align__(16) float Bs[2][16][128];

    const float* A  = blockIdx.z ? Wv : Wq;
    const float* Bm = blockIdx.z ? Wp : wkt;
    float* C        = blockIdx.z ? wvp : mqk;
    const int Nn = H_, K = H_;

    const int tid = threadIdx.x;
    const int bx = blockIdx.x, by = blockIdx.y;
    const int arow = tid >> 1, acol = (tid & 1) << 3;
    const int brow = tid >> 4, bcol = (tid & 15) << 3;
    const int tx = tid & 15, ty = tid >> 4;

    const float* Ap = A + ((size_t)by * 128 + arow) * K + acol;
    const float* Bp = Bm + (size_t)brow * Nn + (size_t)bx * 128 + bcol;

    uint32_t bdst0 = (uint32_t)__cvta_generic_to_shared(&Bs[0][brow][bcol]);
    uint32_t bdst1 = (uint32_t)__cvta_generic_to_shared(&Bs[1][brow][bcol]);

    u64 acc[8][4];
#pragma unroll
    for (int i = 0; i < 8; i++)
#pragma unroll
        for (int j = 0; j < 4; j++) acc[i][j] = 0ull;

    {
        float4 av0 = *(const float4*)(Ap);
        float4 av1 = *(const float4*)(Ap + 4);
        As[0][acol+0][arow] = av0.x;
        As[0][acol+1][arow] = av0.y;
        As[0][acol+2][arow] = av0.z;
        As[0][acol+3][arow] = av0.w;
        As[0][acol+4][arow] = av1.x;
        As[0][acol+5][arow] = av1.y;
        As[0][acol+6][arow] = av1.z;
        As[0][acol+7][arow] = av1.w;
        cp_async16(bdst0,      Bp);
        cp_async16(bdst0 + 16, Bp + 4);
        cp_commit();
        cp_wait0();
    }
    __syncthreads();

    int buf = 0;
    for (int k0 = 16; k0 <= K; k0 += 16) {
        const bool more = (k0 < K);
        float4 av0, av1;
        if (more) {
            av0 = *(const float4*)(Ap + k0);
            av1 = *(const float4*)(Ap + k0 + 4);
            uint32_t bd = buf ? bdst0 : bdst1;
            const float* bsrc = Bp + (size_t)k0 * Nn;
            cp_async16(bd,      bsrc);
            cp_async16(bd + 16, bsrc + 4);
            cp_commit();
        }
        const float (*Asb)[132] = As[buf];
        const float (*Bsb)[128] = Bs[buf];
#pragma unroll
        for (int kk = 0; kk < 16; kk++) {
            float a[8];
            *(float4*)(a)   = *(const float4*)&Asb[kk][ty*8];
            *(float4*)(a+4) = *(const float4*)&Asb[kk][ty*8+4];
            ulonglong2 bp0 = *(const ulonglong2*)&Bsb[kk][tx*4];
            ulonglong2 bp1 = *(const ulonglong2*)&Bsb[kk][64 + tx*4];
            u64 b2[4] = { bp0.x, bp0.y, bp1.x, bp1.y };
#pragma unroll
            for (int i = 0; i < 8; i++) {
                u64 ad = dup2(a[i]);
#pragma unroll
                for (int j = 0; j < 4; j++)
                    acc[i][j] = fma2(ad, b2[j], acc[i][j]);
            }
        }
        if (more) {
            const int nb = buf ^ 1;
            As[nb][acol+0][arow] = av0.x;
            As[nb][acol+1][arow] = av0.y;
            As[nb][acol+2][arow] = av0.z;
            As[nb][acol+3][arow] = av0.w;
            As[nb][acol+4][arow] = av1.x;
            As[nb][acol+5][arow] = av1.y;
            As[nb][acol+6][arow] = av1.z;
            As[nb][acol+7][arow] = av1.w;
            cp_wait0();
            __syncthreads();
            buf = nb;
        }
    }

    const int crow0 = by * 128 + ty * 8;
    const int c0 = bx * 128 + tx * 4;
#pragma unroll
    for (int i = 0; i < 8; i++) {
        size_t rbase = (size_t)(crow0 + i) * Nn;
#pragma unroll
        for (int g = 0; g < 2; g++) {
            const int col = c0 + g * 64;
            float2 p0 = unpack2(acc[i][g*2 + 0]);
            float2 p1 = unpack2(acc[i][g*2 + 1]);
            float4 o;
            o.x = p0.x; o.y = p0.y; o.z = p1.x; o.w = p1.y;
            *(float4*)(C + rbase + col) = o;
        }
    }
}

// ---------------- Temporal attention (folded form) -------------------------
// scores_ts = ((q'_t + u) . h_s) * scale ; out = P @ h
#define HP_ 260
__global__ void __launch_bounds__(256) attn_kernel(
    const float* __restrict__ qp, const float* __restrict__ h,
    const float* __restrict__ u, float* __restrict__ out) {
    extern __shared__ float smf[];
    float* q_s = smf;                 // [20][260]  (q' + u)
    float* h_s = smf + T_*HP_;        // [20][260]
    float* s_s = smf + 2*T_*HP_;      // [20][20]

    const int bn = blockIdx.x;
    const int n = bn >> 6, b = bn & 63;
    const size_t row0 = (size_t)n * BT_ + (size_t)b * T_;
    const int tid = threadIdx.x;
    const int wid = tid >> 5, lane = tid & 31;

    for (int idx = tid; idx < T_ * (H_/4); idx += 256) {
        int t = idx >> 6, hc = idx & 63;
        float4 qv = ((const float4*)(qp + (row0 + t) * H_))[hc];
        float4 uu = ((const float4*)u)[hc];
        qv.x += uu.x; qv.y += uu.y; qv.z += uu.z; qv.w += uu.w;
        *(float4*)(q_s + t * HP_ + hc * 4) = qv;
        *(float4*)(h_s + t * HP_ + hc * 4) =
            ((const float4*)(h + (row0 + t) * H_))[hc];
    }
    __syncthreads();

    for (int p = tid; p < T_*T_; p += 256) {
        int t = p / T_, s = p - t * T_;
        float ax = 0.f, ay = 0.f, az = 0.f, aw = 0.f;
        const float4* qq = (const float4*)(q_s + t * HP_);
        const float4* hh = (const float4*)(h_s + s * HP_);
#pragma unroll 8
        for (int hc = 0; hc < H_/4; hc++) {
            float4 qv = qq[hc];
            float4 hv = hh[hc];
            ax = fmaf(qv.x, hv.x, ax);
            ay = fmaf(qv.y, hv.y, ay);
            az = fmaf(qv.z, hv.z, az);
            aw = fmaf(qv.w, hv.w, aw);
        }
        s_s[t*T_ + s] = (ax + ay + az + aw) * 0.0625f;   // 1/sqrt(256)
    }
    __syncthreads();

    // warp-parallel softmax: warp w handles rows t = w, w+8, ...
    for (int t = wid; t < T_; t += 8) {
        float v = (lane < T_) ? s_s[t*T_ + lane] : -1e30f;
        float mx = v;
#pragma unroll
        for (int off = 16; off; off >>= 1)
            mx = fmaxf(mx, __shfl_xor_sync(0xffffffffu, mx, off));
        float e = (lane < T_) ? __expf(v - mx) : 0.f;
        float sum = e;
#pragma unroll
        for (int off = 16; off; off >>= 1)
            sum += __shfl_xor_sync(0xffffffffu, sum, off);
        if (lane < T_) s_s[t*T_ + lane] = e / sum;
    }
    __syncthreads();

    for (int idx = tid; idx < T_ * (H_/4); idx += 256) {
        int t = idx >> 6, hc = idx & 63;
        float4 acc = make_float4(0.f, 0.f, 0.f, 0.f);
#pragma unroll
        for (int s = 0; s < T_; s++) {
            float p = s_s[t*T_ + s];
            float4 hv = *(const float4*)(h_s + s * HP_ + hc * 4);
            acc.x = fmaf(p, hv.x, acc.x);
            acc.y = fmaf(p, hv.y, acc.y);
            acc.z = fmaf(p, hv.z, acc.z);
            acc.w = fmaf(p, hv.w, acc.w);
        }
        ((float4*)(out + (row0 + t) * H_))[hc] = acc;
    }
}

// ---------------- LayerNorm + scatter back to [b,t,n,h] -------------------
__inline__ __device__ float warp_sum(float val) {
#pragma unroll
    for (int o = 16; o; o >>= 1) val += __shfl_xor_sync(0xffffffffu, val, o);
    return val;
}

__global__ void __launch_bounds__(256) ln_kernel(
    const float* __restrict__ a, const float* __restrict__ gamma,
    const float* __restrict__ beta, float* __restrict__ out) {
    const int row  = blockIdx.x * 8 + (threadIdx.x >> 5);   // n*BT + bt
    const int lane = threadIdx.x & 31;
    const float4* ap = (const float4*)(a + (size_t)row * H_);
    float4 v0 = ap[lane];
    float4 v1 = ap[lane + 32];

    float s = v0.x + v0.y + v0.z + v0.w + v1.x + v1.y + v1.z + v1.w;
    s = warp_sum(s);
    float mean = s * (1.f / H_);

    float d, sq = 0.f;
    d = v0.x - mean; sq = fmaf(d, d, sq);
    d = v0.y - mean; sq = fmaf(d, d, sq);
    d = v0.z - mean; sq = fmaf(d, d, sq);
    d = v0.w - mean; sq = fmaf(d, d, sq);
    d = v1.x - mean; sq = fmaf(d, d, sq);
    d = v1.y - mean; sq = fmaf(d, d, sq);
    d = v1.z - mean; sq = fmaf(d, d, sq);
    d = v1.w - mean; sq = fmaf(d, d, sq);
    sq = warp_sum(sq);
    float rstd = rsqrtf(sq * (1.f / H_) + LN_EPS);

    float4 g0 = ((const float4*)gamma)[lane];
    float4 g1 = ((const float4*)gamma)[lane + 32];
    float4 be0 = ((const float4*)beta)[lane];
    float4 be1 = ((const float4*)beta)[lane + 32];

    float4 o0, o1;
    o0.x = (v0.x - mean) * rstd * g0.x + be0.x;
    o0.y = (v0.y - mean) * rstd * g0.y + be0.y;
    o0.z = (v0.z - mean) * rstd * g0.z + be0.z;
    o0.w = (v0.w - mean) * rstd * g0.w + be0.w;
    o1.x = (v1.x - mean) * rstd * g1.x + be1.x;
    o1.y = (v1.y - mean) * rstd * g1.y + be1.y;
    o1.z = (v1.z - mean) * rstd * g1.z + be1.z;
    o1.w = (v1.w - mean) * rstd * g1.w + be1.w;

    const int n = row / BT_, bt = row % BT_;
    float4* op = (float4*)(out + ((size_t)bt * N_ + n) * H_);
    op[lane] = o0;
    op[lane + 32] = o1;
}

// ---------------- host launcher -------------------------------------------
extern "C" void kernel_launch(void* const* d_in, const int* in_sizes, int n_in,
                              void* d_out, int out_size) {
    const float* x     = (const float*)d_in[0];
    const float* adj   = (const float*)d_in[1];
    const float* W0    = (const float*)d_in[2];
    const float* b0    = (const float*)d_in[3];
    const float* W1    = (const float*)d_in[4];
    const float* b1    = (const float*)d_in[5];
    const float* W2    = (const float*)d_in[6];
    const float* b2    = (const float*)d_in[7];
    const float* Wq    = (const float*)d_in[8];
    const float* bq    = (const float*)d_in[9];
    const float* Wk    = (const float*)d_in[10];
    const float* bk    = (const float*)d_in[11];  // t-const in softmax: drops
    const float* Wv    = (const float*)d_in[12];
    const float* bv    = (const float*)d_in[13];
    const float* Wp    = (const float*)d_in[14];
    const float* bp    = (const float*)d_in[15];
    const float* gamma = (const float*)d_in[16];
    const float* beta  = (const float*)d_in[17];
    float* outp = (float*)d_out;
    (void)bk;

    float *xT, *m, *h0, *h1, *qv, *adjp, *wkt, *mqk, *wvp, *u, *bvp;
    cudaGetSymbolAddress((void**)&xT,   g_x);
    cudaGetSymbolAddress((void**)&m,    g_m);
    cudaGetSymbolAddress((void**)&h0,   g_h0);
    cudaGetSymbolAddress((void**)&h1,   g_h1);
    cudaGetSymbolAddress((void**)&qv,   g_qv);
    cudaGetSymbolAddress((void**)&adjp, g_adjp);
    cudaGetSymbolAddress((void**)&wkt,  g_wkt);
    cudaGetSymbolAddress((void**)&mqk,  g_mqk);
    cudaGetSymbolAddress((void**)&wvp,  g_wvp);
    cudaGetSymbolAddress((void**)&u,    g_u);
    cudaGetSymbolAddress((void**)&bvp,  g_bvp);

    const int attn_smem = (2*T_*HP_ + T_*T_) * sizeof(float);  // 43200 B
    cudaFuncSetAttribute(attn_kernel, cudaFuncAttributeMaxDynamicSharedMemorySize,
                         attn_smem);

    // ---- prep ----
    prep_misc<<<345, 256>>>(adj, Wk, bq, bv, Wp, bp, adjp, wkt, u, bvp);
    xpose_kernel<<<(BTN_*(F_/4) + 255)/256, 256>>>(x, xT);
    prep_gemm<<<dim3(2, 2, 2), 256>>>(Wq, wkt, Wv, Wp, mqk, wvp);

    // ---- GCN stack (msg GEMMs use K=112 zero-padded) ----
    sgemm_kernel<false,false,false,true><<<dim3(BT_*F_/128, 1), 128>>>(
        adjp, xT, nullptr, nullptr, m, NP_, BT_*F_, KP_, N_);
    sgemm_kernel<true,true,false,false><<<dim3(2, 1000), 128>>>(
        m, W0, b0, nullptr, h0, BTN_, H_, F_, BTN_);

    sgemm_kernel<false,false,false,true><<<dim3(BT_*H_/128, 1), 128>>>(
        adjp, h0, nullptr, nullptr, m, NP_, BT_*H_, KP_, N_);
    sgemm_kernel<true,true,true,false><<<dim3(2, 1000), 128>>>(
        m, W1, b1, h0, h1, BTN_, H_, H_, BTN_);

    sgemm_kernel<false,false,false,true><<<dim3(BT_*H_/128, 1), 128>>>(
        adjp, h1, nullptr, nullptr, m, NP_, BT_*H_, KP_, N_);
    sgemm_kernel<true,true,true,false><<<dim3(2, 1000), 128>>>(
        m, W2, b2, h1, h0, BTN_, H_, H_, BTN_);

    // ---- folded attention path ----
    sgemm_kernel<false,false,false,false><<<dim3(2, 1000), 128>>>(
        h0, mqk, nullptr, nullptr, qv, BTN_, H_, H_, BTN_);

    attn_kernel<<<N_*B_, 256, attn_smem>>>(qv, h0, u, m);

    sgemm_kernel<true,false,false,false><<<dim3(2, 1000), 128>>>(
        m, wvp, bvp, nullptr, h1, BTN_, H_, H_, BTN_);

    // layernorm + scatter to [b,t,n,h]
    ln_kernel<<<BTN_/8, 256>>>(h1, gamma, beta, outp);
}

// round 15
// speedup vs baseline: 1.2400x; 1.2400x over previous
#include <cuda_runtime.h>
#include <math.h>
#include <stdint.h>

#define B_   64
#define T_   20
#define N_   100
#define F_   64
#define H_   256
#define BT_  (B_*T_)        // 1280
#define BTN_ (B_*T_*N_)     // 128000
#define NP_  128            // padded node count (M side)
#define KP_  112            // padded node count (K side, 7x16)
#define LN_EPS 1e-5f

typedef unsigned long long u64;

// ---------------- f32x2 packed-math helpers (sm_103a) ----------------------
__device__ __forceinline__ u64 fma2(u64 a, u64 b, u64 c) {
    u64 d;
    asm("fma.rn.f32x2 %0, %1, %2, %3;" : "=l"(d) : "l"(a), "l"(b), "l"(c));
    return d;
}
__device__ __forceinline__ u64 dup2(float x) {
    u64 d;
    asm("mov.b64 %0, {%1, %1};" : "=l"(d) : "f"(x));
    return d;
}
__device__ __forceinline__ float2 unpack2(u64 v) {
    float2 r;
    asm("mov.b64 {%0, %1}, %2;" : "=f"(r.x), "=f"(r.y) : "l"(v));
    return r;
}

// ---------------- cp.async helpers -----------------------------------------
__device__ __forceinline__ void cp_async16(uint32_t sa, const void* gp) {
    asm volatile("cp.async.ca.shared.global [%0], [%1], 16;" :: "r"(sa), "l"(gp));
}
__device__ __forceinline__ void cp_commit() {
    asm volatile("cp.async.commit_group;");
}
__device__ __forceinline__ void cp_wait0() {
    asm volatile("cp.async.wait_group 0;");
}

// ---------------- scratch (static device globals; no allocation) ----------
__device__ float g_x   [NP_*BT_*F_];     // x transposed, node-major (rows>=100 zero)
__device__ float g_m   [N_*BT_*H_];      // msg / attn scratch
__device__ float g_h0  [NP_*BT_*H_];     // node-padded rows stay zero
__device__ float g_h1  [NP_*BT_*H_];
__device__ float g_qv  [BTN_*H_];        // q' = h @ (Wq Wk^T)
__device__ float g_adjp[NP_*KP_];        // zero-padded adjacency [128][112]
__device__ float g_wkt [H_*H_];          // Wk^T
__device__ float g_mqk [H_*H_];          // Wq @ Wk^T
__device__ float g_wvp [H_*H_];          // Wv @ Wp
__device__ float g_u   [H_];             // Wk @ bq
__device__ float g_bvp [H_];             // bv @ Wp + bp

// ---------------- merged misc prep ----------------------------------------
// blocks [0,56):    adjp[n*112+m] (128x112, zero-padded)
// blocks [56,312):  wkt[o*256+g] = Wk[g*256+o]
// blocks [312,344): u[g] = Wk[g,:]·bq  (warp per g)
// block  344:       bvp[o] = bp[o] + sum_f bv[f]*Wp[f][o]
__global__ void prep_misc(const float* __restrict__ adj,
                          const float* __restrict__ Wk,
                          const float* __restrict__ bq,
                          const float* __restrict__ bv,
                          const float* __restrict__ Wp,
                          const float* __restrict__ bp,
                          float* __restrict__ adjp, float* __restrict__ wkt,
                          float* __restrict__ u, float* __restrict__ bvp) {
    const int tid = threadIdx.x;
    const int blk = blockIdx.x;
    if (blk < 56) {
        int i = blk * 256 + tid;                  // 128*112 = 14336
        if (i < NP_*KP_) {
            int n = i / KP_, m2 = i - n * KP_;
            adjp[i] = (n < N_ && m2 < N_) ? adj[n * N_ + m2] : 0.f;
        }
    } else if (blk < 312) {
        int i = (blk - 56) * 256 + tid;           // 65536
        int o = i >> 8, g = i & 255;
        wkt[i] = Wk[g * H_ + o];
    } else if (blk < 344) {
        const int g = (blk - 312) * 8 + (tid >> 5);
        const int lane = tid & 31;
        float s = 0.f;
#pragma unroll
        for (int i = 0; i < 8; i++) {
            int o = lane + 32 * i;
            s = fmaf(Wk[g * H_ + o], bq[o], s);
        }
#pragma unroll
        for (int off = 16; off; off >>= 1)
            s += __shfl_xor_sync(0xffffffffu, s, off);
        if (lane == 0) u[g] = s;
    } else {
        const int o = tid;
        float s0 = bp[o], s1 = 0.f, s2 = 0.f, s3 = 0.f;
        for (int f = 0; f < H_; f += 4) {
            s0 = fmaf(bv[f+0], Wp[(f+0) * H_ + o], s0);
            s1 = fmaf(bv[f+1], Wp[(f+1) * H_ + o], s1);
            s2 = fmaf(bv[f+2], Wp[(f+2) * H_ + o], s2);
            s3 = fmaf(bv[f+3], Wp[(f+3) * H_ + o], s3);
        }
        bvp[o] = (s0 + s1) + (s2 + s3);
    }
}

// x[b,t,n,f] -> g_x[(n*BT + bt)*F + f]
__global__ void xpose_kernel(const float* __restrict__ x, float* __restrict__ xT) {
    int idx = blockIdx.x * 256 + threadIdx.x;
    if (idx >= BTN_ * (F_/4)) return;
    int c   = idx & 15;
    int row = idx >> 4;            // bt*100 + n
    int n   = row % N_;
    int bt  = row / N_;
    ((float4*)xT)[(n * BT_ + bt) * (F_/4) + c] = ((const float4*)x)[idx];
}

// ---------------- SGEMM: 128 threads, 16x8 thread tile, f32x2 core ---------
// C[M,Nn] = A[M,K] @ B[K,Nn] (+bias)(relu)(+res). 128x128 CTA tile, Kstep 16.
// NOTE: occupancy 2 (NOT 3 — reg cap to 170 spills and regressed in R14).
template<bool BIAS, bool RELU, bool RES, bool MG>
__global__ void __launch_bounds__(128, 2) sgemm_kernel(
    const float* __restrict__ A, const float* __restrict__ Bm,
    const float* __restrict__ bias, const float* __restrict__ res,
    float* __restrict__ C, int M, int Nn, int K, int Mvalid) {
    __shared__ __align__(16) float As[2][16][132];
    __shared__ __align__(16) float Bs[2][16][128];

    const int tid = threadIdx.x;
    const int bx = blockIdx.x, by = blockIdx.y;
    const int arow = tid;                              // one A row per thread
    const int brow = tid >> 5, bcol = (tid & 31) << 2; // B: 4 rows per pass
    const int tx = tid & 15, ty = tid >> 4;

    const float* Ap = A + ((size_t)by * 128 + arow) * K;
    const float* Bp = Bm + (size_t)brow * Nn + (size_t)bx * 128 + bcol;

    uint32_t bdst0 = (uint32_t)__cvta_generic_to_shared(&Bs[0][brow][bcol]);
    uint32_t bdst1 = (uint32_t)__cvta_generic_to_shared(&Bs[1][brow][bcol]);

    u64 acc[16][4];
#pragma unroll
    for (int i = 0; i < 16; i++)
#pragma unroll
        for (int j = 0; j < 4; j++) acc[i][j] = 0ull;

    // prologue: k-block 0 -> buf 0
    {
#pragma unroll
        for (int c = 0; c < 4; c++) {
            float4 av = *(const float4*)(Ap + c * 4);
            As[0][c*4+0][arow] = av.x;
            As[0][c*4+1][arow] = av.y;
            As[0][c*4+2][arow] = av.z;
            As[0][c*4+3][arow] = av.w;
        }
#pragma unroll
        for (int i = 0; i < 4; i++)
            cp_async16(bdst0 + i * 4 * 128 * 4, Bp + (size_t)(i * 4) * Nn);
        cp_commit();
        cp_wait0();
    }
    __syncthreads();

    int buf = 0;
    for (int k0 = 16; k0 <= K; k0 += 16) {
        const bool more = (k0 < K);
        float4 av[4];
        if (more) {
#pragma unroll
            for (int c = 0; c < 4; c++)
                av[c] = *(const float4*)(Ap + k0 + c * 4);
            uint32_t bd = buf ? bdst0 : bdst1;   // next buffer
#pragma unroll
            for (int i = 0; i < 4; i++)
                cp_async16(bd + i * 4 * 128 * 4,
                           Bp + (size_t)(k0 + i * 4) * Nn);
            cp_commit();
        }

        const float (*Asb)[132] = As[buf];
        const float (*Bsb)[128] = Bs[buf];
#pragma unroll
        for (int kk = 0; kk < 16; kk++) {
            float a[16];
            *(float4*)(a)    = *(const float4*)&Asb[kk][ty*16];
            *(float4*)(a+4)  = *(const float4*)&Asb[kk][ty*16+4];
            *(float4*)(a+8)  = *(const float4*)&Asb[kk][ty*16+8];
            *(float4*)(a+12) = *(const float4*)&Asb[kk][ty*16+12];
            ulonglong2 bp0 = *(const ulonglong2*)&Bsb[kk][tx*4];
            ulonglong2 bp1 = *(const ulonglong2*)&Bsb[kk][64 + tx*4];
            u64 b2[4] = { bp0.x, bp0.y, bp1.x, bp1.y };
#pragma unroll
            for (int i = 0; i < 16; i++) {
                u64 ad = dup2(a[i]);
#pragma unroll
                for (int j = 0; j < 4; j++)
                    acc[i][j] = fma2(ad, b2[j], acc[i][j]);
            }
        }

        if (more) {
            const int nb = buf ^ 1;
#pragma unroll
            for (int c = 0; c < 4; c++) {
                As[nb][c*4+0][arow] = av[c].x;
                As[nb][c*4+1][arow] = av[c].y;
                As[nb][c*4+2][arow] = av[c].z;
                As[nb][c*4+3][arow] = av[c].w;
            }
            cp_wait0();
            __syncthreads();
            buf = nb;
        }
    }

    const int crow0 = by * 128 + ty * 16;
    const int c0 = bx * 128 + tx * 4;
#pragma unroll
    for (int i = 0; i < 16; i++) {
        if (MG && (crow0 + i) >= Mvalid) continue;
        size_t rbase = (size_t)(crow0 + i) * Nn;
#pragma unroll
        for (int g = 0; g < 2; g++) {
            const int col = c0 + g * 64;
            float2 p0 = unpack2(acc[i][g*2 + 0]);
            float2 p1 = unpack2(acc[i][g*2 + 1]);
            float4 o;
            o.x = p0.x; o.y = p0.y; o.z = p1.x; o.w = p1.y;
            if (BIAS) {
                o.x += bias[col + 0];
                o.y += bias[col + 1];
                o.z += bias[col + 2];
                o.w += bias[col + 3];
            }
            if (RELU) {
                o.x = fmaxf(o.x, 0.f); o.y = fmaxf(o.y, 0.f);
                o.z = fmaxf(o.z, 0.f); o.w = fmaxf(o.w, 0.f);
            }
            if (RES) {
                float4 r = *(const float4*)(res + rbase + col);
                o.x += r.x; o.y += r.y; o.z += r.z; o.w += r.w;
            }
            *(float4*)(C + rbase + col) = o;
        }
    }
}

// fused prep GEMM (256-thread body, tiny): z=0 -> mqk, z=1 -> wvp
__global__ void __launch_bounds__(256, 2) prep_gemm(
    const float* __restrict__ Wq, const float* __restrict__ wkt,
    const float* __restrict__ Wv, const float* __restrict__ Wp,
    float* __restrict__ mqk, float* __restrict__ wvp) {
    __shared__ __align__(16) float As[2][16][132];
    __shared__ __align__(16) float Bs[2][16][128];

    const float* A  = blockIdx.z ? Wv : Wq;
    const float* Bm = blockIdx.z ? Wp : wkt;
    float* C        = blockIdx.z ? wvp : mqk;
    const int Nn = H_, K = H_;

    const int tid = threadIdx.x;
    const int bx = blockIdx.x, by = blockIdx.y;
    const int arow = tid >> 1, acol = (tid & 1) << 3;
    const int brow = tid >> 4, bcol = (tid & 15) << 3;
    const int tx = tid & 15, ty = tid >> 4;

    const float* Ap = A + ((size_t)by * 128 + arow) * K + acol;
    const float* Bp = Bm + (size_t)brow * Nn + (size_t)bx * 128 + bcol;

    uint32_t bdst0 = (uint32_t)__cvta_generic_to_shared(&Bs[0][brow][bcol]);
    uint32_t bdst1 = (uint32_t)__cvta_generic_to_shared(&Bs[1][brow][bcol]);

    u64 acc[8][4];
#pragma unroll
    for (int i = 0; i < 8; i++)
#pragma unroll
        for (int j = 0; j < 4; j++) acc[i][j] = 0ull;

    {
        float4 av0 = *(const float4*)(Ap);
        float4 av1 = *(const float4*)(Ap + 4);
        As[0][acol+0][arow] = av0.x;
        As[0][acol+1][arow] = av0.y;
        As[0][acol+2][arow] = av0.z;
        As[0][acol+3][arow] = av0.w;
        As[0][acol+4][arow] = av1.x;
        As[0][acol+5][arow] = av1.y;
        As[0][acol+6][arow] = av1.z;
        As[0][acol+7][arow] = av1.w;
        cp_async16(bdst0,      Bp);
        cp_async16(bdst0 + 16, Bp + 4);
        cp_commit();
        cp_wait0();
    }
    __syncthreads();

    int buf = 0;
    for (int k0 = 16; k0 <= K; k0 += 16) {
        const bool more = (k0 < K);
        float4 av0, av1;
        if (more) {
            av0 = *(const float4*)(Ap + k0);
            av1 = *(const float4*)(Ap + k0 + 4);
            uint32_t bd = buf ? bdst0 : bdst1;
            const float* bsrc = Bp + (size_t)k0 * Nn;
            cp_async16(bd,      bsrc);
            cp_async16(bd + 16, bsrc + 4);
            cp_commit();
        }
        const float (*Asb)[132] = As[buf];
        const float (*Bsb)[128] = Bs[buf];
#pragma unroll
        for (int kk = 0; kk < 16; kk++) {
            float a[8];
            *(float4*)(a)   = *(const float4*)&Asb[kk][ty*8];
            *(float4*)(a+4) = *(const float4*)&Asb[kk][ty*8+4];
            ulonglong2 bp0 = *(const ulonglong2*)&Bsb[kk][tx*4];
            ulonglong2 bp1 = *(const ulonglong2*)&Bsb[kk][64 + tx*4];
            u64 b2[4] = { bp0.x, bp0.y, bp1.x, bp1.y };
#pragma unroll
            for (int i = 0; i < 8; i++) {
                u64 ad = dup2(a[i]);
#pragma unroll
                for (int j = 0; j < 4; j++)
                    acc[i][j] = fma2(ad, b2[j], acc[i][j]);
            }
        }
        if (more) {
            const int nb = buf ^ 1;
            As[nb][acol+0][arow] = av0.x;
            As[nb][acol+1][arow] = av0.y;
            As[nb][acol+2][arow] = av0.z;
            As[nb][acol+3][arow] = av0.w;
            As[nb][acol+4][arow] = av1.x;
            As[nb][acol+5][arow] = av1.y;
            As[nb][acol+6][arow] = av1.z;
            As[nb][acol+7][arow] = av1.w;
            cp_wait0();
            __syncthreads();
            buf = nb;
        }
    }

    const int crow0 = by * 128 + ty * 8;
    const int c0 = bx * 128 + tx * 4;
#pragma unroll
    for (int i = 0; i < 8; i++) {
        size_t rbase = (size_t)(crow0 + i) * Nn;
#pragma unroll
        for (int g = 0; g < 2; g++) {
            const int col = c0 + g * 64;
            float2 p0 = unpack2(acc[i][g*2 + 0]);
            float2 p1 = unpack2(acc[i][g*2 + 1]);
            float4 o;
            o.x = p0.x; o.y = p0.y; o.z = p1.x; o.w = p1.y;
            *(float4*)(C + rbase + col) = o;
        }
    }
}

// ---------------- Temporal attention (folded form) -------------------------
// scores_ts = ((q'_t + u) . h_s) * scale ; out = P @ h
#define HP_ 260
__global__ void __launch_bounds__(256) attn_kernel(
    const float* __restrict__ qp, const float* __restrict__ h,
    const float* __restrict__ u, float* __restrict__ out) {
    extern __shared__ float smf[];
    float* q_s = smf;                 // [20][260]  (q' + u)
    float* h_s = smf + T_*HP_;        // [20][260]
    float* s_s = smf + 2*T_*HP_;      // [20][20]

    const int bn = blockIdx.x;
    const int n = bn >> 6, b = bn & 63;
    const size_t row0 = (size_t)n * BT_ + (size_t)b * T_;
    const int tid = threadIdx.x;
    const int wid = tid >> 5, lane = tid & 31;

    for (int idx = tid; idx < T_ * (H_/4); idx += 256) {
        int t = idx >> 6, hc = idx & 63;
        float4 qv = ((const float4*)(qp + (row0 + t) * H_))[hc];
        float4 uu = ((const float4*)u)[hc];
        qv.x += uu.x; qv.y += uu.y; qv.z += uu.z; qv.w += uu.w;
        *(float4*)(q_s + t * HP_ + hc * 4) = qv;
        *(float4*)(h_s + t * HP_ + hc * 4) =
            ((const float4*)(h + (row0 + t) * H_))[hc];
    }
    __syncthreads();

    for (int p = tid; p < T_*T_; p += 256) {
        int t = p / T_, s = p - t * T_;
        float ax = 0.f, ay = 0.f, az = 0.f, aw = 0.f;
        const float4* qq = (const float4*)(q_s + t * HP_);
        const float4* hh = (const float4*)(h_s + s * HP_);
#pragma unroll 8
        for (int hc = 0; hc < H_/4; hc++) {
            float4 qv = qq[hc];
            float4 hv = hh[hc];
            ax = fmaf(qv.x, hv.x, ax);
            ay = fmaf(qv.y, hv.y, ay);
            az = fmaf(qv.z, hv.z, az);
            aw = fmaf(qv.w, hv.w, aw);
        }
        s_s[t*T_ + s] = (ax + ay + az + aw) * 0.0625f;   // 1/sqrt(256)
    }
    __syncthreads();

    // warp-parallel softmax: warp w handles rows t = w, w+8, ...
    for (int t = wid; t < T_; t += 8) {
        float v = (lane < T_) ? s_s[t*T_ + lane] : -1e30f;
        float mx = v;
#pragma unroll
        for (int off = 16; off; off >>= 1)
            mx = fmaxf(mx, __shfl_xor_sync(0xffffffffu, mx, off));
        float e = (lane < T_) ? __expf(v - mx) : 0.f;
        float sum = e;
#pragma unroll
        for (int off = 16; off; off >>= 1)
            sum += __shfl_xor_sync(0xffffffffu, sum, off);
        if (lane < T_) s_s[t*T_ + lane] = e / sum;
    }
    __syncthreads();

    for (int idx = tid; idx < T_ * (H_/4); idx += 256) {
        int t = idx >> 6, hc = idx & 63;
        float4 acc = make_float4(0.f, 0.f, 0.f, 0.f);
#pragma unroll
        for (int s = 0; s < T_; s++) {
            float p = s_s[t*T_ + s];
            float4 hv = *(const float4*)(h_s + s * HP_ + hc * 4);
            acc.x = fmaf(p, hv.x, acc.x);
            acc.y = fmaf(p, hv.y, acc.y);
            acc.z = fmaf(p, hv.z, acc.z);
            acc.w = fmaf(p, hv.w, acc.w);
        }
        ((float4*)(out + (row0 + t) * H_))[hc] = acc;
    }
}

// ---------------- LayerNorm + scatter back to [b,t,n,h] -------------------
__inline__ __device__ float warp_sum(float val) {
#pragma unroll
    for (int o = 16; o; o >>= 1) val += __shfl_xor_sync(0xffffffffu, val, o);
    return val;
}

__global__ void __launch_bounds__(256) ln_kernel(
    const float* __restrict__ a, const float* __restrict__ gamma,
    const float* __restrict__ beta, float* __restrict__ out) {
    const int row  = blockIdx.x * 8 + (threadIdx.x >> 5);   // n*BT + bt
    const int lane = threadIdx.x & 31;
    const float4* ap = (const float4*)(a + (size_t)row * H_);
    float4 v0 = ap[lane];
    float4 v1 = ap[lane + 32];

    float s = v0.x + v0.y + v0.z + v0.w + v1.x + v1.y + v1.z + v1.w;
    s = warp_sum(s);
    float mean = s * (1.f / H_);

    float d, sq = 0.f;
    d = v0.x - mean; sq = fmaf(d, d, sq);
    d = v0.y - mean; sq = fmaf(d, d, sq);
    d = v0.z - mean; sq = fmaf(d, d, sq);
    d = v0.w - mean; sq = fmaf(d, d, sq);
    d = v1.x - mean; sq = fmaf(d, d, sq);
    d = v1.y - mean; sq = fmaf(d, d, sq);
    d = v1.z - mean; sq = fmaf(d, d, sq);
    d = v1.w - mean; sq = fmaf(d, d, sq);
    sq = warp_sum(sq);
    float rstd = rsqrtf(sq * (1.f / H_) + LN_EPS);

    float4 g0 = ((const float4*)gamma)[lane];
    float4 g1 = ((const float4*)gamma)[lane + 32];
    float4 be0 = ((const float4*)beta)[lane];
    float4 be1 = ((const float4*)beta)[lane + 32];

    float4 o0, o1;
    o0.x = (v0.x - mean) * rstd * g0.x + be0.x;
    o0.y = (v0.y - mean) * rstd * g0.y + be0.y;
    o0.z = (v0.z - mean) * rstd * g0.z + be0.z;
    o0.w = (v0.w - mean) * rstd * g0.w + be0.w;
    o1.x = (v1.x - mean) * rstd * g1.x + be1.x;
    o1.y = (v1.y - mean) * rstd * g1.y + be1.y;
    o1.z = (v1.z - mean) * rstd * g1.z + be1.z;
    o1.w = (v1.w - mean) * rstd * g1.w + be1.w;

    const int n = row / BT_, bt = row % BT_;
    float4* op = (float4*)(out + ((size_t)bt * N_ + n) * H_);
    op[lane] = o0;
    op[lane + 32] = o1;
}

// ---------------- host launcher -------------------------------------------
extern "C" void kernel_launch(void* const* d_in, const int* in_sizes, int n_in,
                              void* d_out, int out_size) {
    const float* x     = (const float*)d_in[0];
    const float* adj   = (const float*)d_in[1];
    const float* W0    = (const float*)d_in[2];
    const float* b0    = (const float*)d_in[3];
    const float* W1    = (const float*)d_in[4];
    const float* b1    = (const float*)d_in[5];
    const float* W2    = (const float*)d_in[6];
    const float* b2    = (const float*)d_in[7];
    const float* Wq    = (const float*)d_in[8];
    const float* bq    = (const float*)d_in[9];
    const float* Wk    = (const float*)d_in[10];
    const float* bk    = (const float*)d_in[11];  // t-const in softmax: drops
    const float* Wv    = (const float*)d_in[12];
    const float* bv    = (const float*)d_in[13];
    const float* Wp    = (const float*)d_in[14];
    const float* bp    = (const float*)d_in[15];
    const float* gamma = (const float*)d_in[16];
    const float* beta  = (const float*)d_in[17];
    float* outp = (float*)d_out;
    (void)bk;

    float *xT, *m, *h0, *h1, *qv, *adjp, *wkt, *mqk, *wvp, *u, *bvp;
    cudaGetSymbolAddress((void**)&xT,   g_x);
    cudaGetSymbolAddress((void**)&m,    g_m);
    cudaGetSymbolAddress((void**)&h0,   g_h0);
    cudaGetSymbolAddress((void**)&h1,   g_h1);
    cudaGetSymbolAddress((void**)&qv,   g_qv);
    cudaGetSymbolAddress((void**)&adjp, g_adjp);
    cudaGetSymbolAddress((void**)&wkt,  g_wkt);
    cudaGetSymbolAddress((void**)&mqk,  g_mqk);
    cudaGetSymbolAddress((void**)&wvp,  g_wvp);
    cudaGetSymbolAddress((void**)&u,    g_u);
    cudaGetSymbolAddress((void**)&bvp,  g_bvp);

    const int attn_smem = (2*T_*HP_ + T_*T_) * sizeof(float);  // 43200 B
    cudaFuncSetAttribute(attn_kernel, cudaFuncAttributeMaxDynamicSharedMemorySize,
                         attn_smem);

    // ---- prep ----
    prep_misc<<<345, 256>>>(adj, Wk, bq, bv, Wp, bp, adjp, wkt, u, bvp);
    xpose_kernel<<<(BTN_*(F_/4) + 255)/256, 256>>>(x, xT);
    prep_gemm<<<dim3(2, 2, 2), 256>>>(Wq, wkt, Wv, Wp, mqk, wvp);

    // ---- GCN stack (msg GEMMs use K=112 zero-padded) ----
    sgemm_kernel<false,false,false,true><<<dim3(BT_*F_/128, 1), 128>>>(
        adjp, xT, nullptr, nullptr, m, NP_, BT_*F_, KP_, N_);
    sgemm_kernel<true,true,false,false><<<dim3(2, 1000), 128>>>(
        m, W0, b0, nullptr, h0, BTN_, H_, F_, BTN_);

    sgemm_kernel<false,false,false,true><<<dim3(BT_*H_/128, 1), 128>>>(
        adjp, h0, nullptr, nullptr, m, NP_, BT_*H_, KP_, N_);
    sgemm_kernel<true,true,true,false><<<dim3(2, 1000), 128>>>(
        m, W1, b1, h0, h1, BTN_, H_, H_, BTN_);

    sgemm_kernel<false,false,false,true><<<dim3(BT_*H_/128, 1), 128>>>(
        adjp, h1, nullptr, nullptr, m, NP_, BT_*H_, KP_, N_);
    sgemm_kernel<true,true,true,false><<<dim3(2, 1000), 128>>>(
        m, W2, b2, h1, h0, BTN_, H_, H_, BTN_);

    // ---- folded attention path ----
    sgemm_kernel<false,false,false,false><<<dim3(2, 1000), 128>>>(
        h0, mqk, nullptr, nullptr, qv, BTN_, H_, H_, BTN_);

    attn_kernel<<<N_*B_, 256, attn_smem>>>(qv, h0, u, m);

    sgemm_kernel<true,false,false,false><<<dim3(2, 1000), 128>>>(
        m, wvp, bvp, nullptr, h1, BTN_, H_, H_, BTN_);

    // layernorm + scatter to [b,t,n,h]
    ln_kernel<<<BTN_/8, 256>>>(h1, gamma, beta, outp);
}